// round 1
// baseline (speedup 1.0000x reference)
#include <cuda_runtime.h>
#include <cuda_bf16.h>
#include <math.h>

// Problem constants (fixed by the reference)
#define BB 8
#define NN 2048
#define HH 512
#define H2 1024
#define MM (BB * NN)          // 16384 total rows
#define NW (NN / 32)          // 64 mask words per row

// ---------------- static device scratch (no allocations allowed) ----------------
__device__ float    g_x[(long)MM * HH];      // embedding output (residual source)
__device__ float    g_t[(long)MM * HH];      // tmp 512-wide
__device__ float    g_h[(long)MM * H2];      // GAT buffer A
__device__ float    g_g2[(long)MM * H2];     // GAT buffer B
__device__ float    g_hw[(long)MM * H2];     // h @ W per layer
__device__ float    g_es[MM];
__device__ float    g_ed[MM];
__device__ float    g_alpha[(long)BB * NN * NN];     // 134 MB attention matrix
__device__ unsigned g_maskbits[(long)BB * NN * NW];  // 16 MB packed transposed mask

__device__ __forceinline__ float lrelu(float x) { return x > 0.f ? x : 0.2f * x; }

// ---------------- mask transpose + bitpack (once; shared by all 3 layers) -------
// mask[b][t][s] = (adj[b][s][t] != 0) || (s == t)
__global__ void mask_kernel(const int* __restrict__ adj) {
    __shared__ int tile[32][33];
    int b = blockIdx.z;
    int t0 = blockIdx.x * 32, s0 = blockIdx.y * 32;
    tile[threadIdx.y][threadIdx.x] =
        adj[((long)b * NN + (s0 + threadIdx.y)) * NN + t0 + threadIdx.x];
    __syncthreads();
    if (threadIdx.y == 0) {
        int t = t0 + threadIdx.x;
        unsigned w = 0u;
        #pragma unroll
        for (int i = 0; i < 32; i++) {
            int s = s0 + i;
            if (tile[i][threadIdx.x] != 0 || s == t) w |= (1u << i);
        }
        g_maskbits[((long)b * NN + t) * NW + (s0 >> 5)] = w;
    }
}

// ---------------- fused features + first embedding linear (K=6) -----------------
__global__ void embed1_kernel(const float* __restrict__ arrivals,
                              const float* __restrict__ departures,
                              const float* __restrict__ hard,
                              const float* __restrict__ timestep,
                              const float* __restrict__ total,
                              const float* __restrict__ W1,
                              const float* __restrict__ b1,
                              float* __restrict__ out) {
    int m = blockIdx.x;          // 0..MM-1
    int f = threadIdx.x;         // 0..HH-1
    int b = m / NN;
    float ts = timestep[b], tot = total[b];
    float arr = arrivals[m], dep = departures[m];
    float tsa = (ts - arr) / (dep - arr);
    float tss = ts / tot;
    float fe[6];
    fe[0] = tsa; fe[1] = tss;
    fe[2] = fmodf(tss, 2.f); fe[3] = fmodf(tss, 4.f); fe[4] = fmodf(tss, 7.f);
    fe[5] = hard[m];
    float acc = b1[f];
    #pragma unroll
    for (int k = 0; k < 6; k++) acc += fe[k] * W1[k * HH + f];
    out[(long)m * HH + f] = acc;
}

// ---------------- generic tiled fp32 GEMM with fused epilogue -------------------
// C = epi(A @ W + bias), A:[M,K] rm, W:[K,Nn] rm. Optional batch via grid.z.
// epilogue: v = acc + bias; if(relu) v = max(v,0); if(res) v += res; v *= rowscale
#define BM 64
#define BN 64
#define BKK 16
__global__ void __launch_bounds__(256, 4)
gemm_kernel(const float* __restrict__ A, const float* __restrict__ Bm,
            const float* __restrict__ bias, const float* __restrict__ res,
            const float* __restrict__ rowscale, float* __restrict__ C,
            int M, int K, int Nn, int relu,
            long sA, long sB, long sC) {
    int bz = blockIdx.z;
    A  += (long)bz * sA;
    Bm += (long)bz * sB;
    C  += (long)bz * sC;
    if (res) res += (long)bz * sC;

    __shared__ float As[BKK][BM + 4];
    __shared__ float Bs[BKK][BN + 4];
    int tx = threadIdx.x, ty = threadIdx.y;
    int tid = ty * 16 + tx;
    int row0 = blockIdx.y * BM, col0 = blockIdx.x * BN;

    float acc[4][4] = {};
    for (int k0 = 0; k0 < K; k0 += BKK) {
        #pragma unroll
        for (int i = 0; i < 4; i++) {
            int idx = tid + i * 256;
            int r = idx >> 4, c = idx & 15;
            As[c][r] = A[(long)(row0 + r) * K + k0 + c];
        }
        #pragma unroll
        for (int i = 0; i < 4; i++) {
            int idx = tid + i * 256;
            int r = idx >> 6, c = idx & 63;
            Bs[r][c] = Bm[(long)(k0 + r) * Nn + col0 + c];
        }
        __syncthreads();
        #pragma unroll
        for (int kk = 0; kk < BKK; kk++) {
            float4 av = *(const float4*)&As[kk][ty * 4];
            float4 bv = *(const float4*)&Bs[kk][tx * 4];
            float a[4] = {av.x, av.y, av.z, av.w};
            float bvv[4] = {bv.x, bv.y, bv.z, bv.w};
            #pragma unroll
            for (int i = 0; i < 4; i++)
                #pragma unroll
                for (int j = 0; j < 4; j++)
                    acc[i][j] += a[i] * bvv[j];
        }
        __syncthreads();
    }

    int col = col0 + tx * 4;
    float bb[4] = {0.f, 0.f, 0.f, 0.f};
    if (bias) { float4 bv = *(const float4*)&bias[col]; bb[0]=bv.x; bb[1]=bv.y; bb[2]=bv.z; bb[3]=bv.w; }
    #pragma unroll
    for (int i = 0; i < 4; i++) {
        int r = row0 + ty * 4 + i;
        float rs = rowscale ? rowscale[r] : 1.f;
        float v[4];
        #pragma unroll
        for (int j = 0; j < 4; j++) {
            float t = acc[i][j] + bb[j];
            if (relu) t = fmaxf(t, 0.f);
            v[j] = t;
        }
        if (res) {
            float4 rv = *(const float4*)&res[(long)r * Nn + col];
            v[0] += rv.x; v[1] += rv.y; v[2] += rv.z; v[3] += rv.w;
        }
        float4 ov = make_float4(v[0] * rs, v[1] * rs, v[2] * rs, v[3] * rs);
        *(float4*)&C[(long)r * Nn + col] = ov;
    }
}

// ---------------- per-row attention coefficients e_src / e_dst ------------------
__global__ void ev_kernel(const float* __restrict__ hw,
                          const float* __restrict__ asrc,
                          const float* __restrict__ adst,
                          float* __restrict__ es, float* __restrict__ ed, int F) {
    int warp = (blockIdx.x * blockDim.x + threadIdx.x) >> 5;
    int lane = threadIdx.x & 31;
    const float* row = hw + (long)warp * F;
    float s = 0.f, d = 0.f;
    for (int f = lane; f < F; f += 32) {
        float v = row[f];
        s += v * asrc[f];
        d += v * adst[f];
    }
    #pragma unroll
    for (int o = 16; o; o >>= 1) {
        s += __shfl_xor_sync(0xffffffffu, s, o);
        d += __shfl_xor_sync(0xffffffffu, d, o);
    }
    if (lane == 0) { es[warp] = s; ed[warp] = d; }
}

// ---------------- masked softmax row -> alpha matrix ----------------------------
// One block per (b, t). lrelu is monotone: row max = lrelu(ed + max_masked(es)).
__global__ void alpha_kernel(const float* __restrict__ es,
                             const float* __restrict__ ed) {
    __shared__ float    ses[NN];
    __shared__ unsigned smask[NW];
    __shared__ float    red[256];
    int t = blockIdx.x, b = blockIdx.y;
    int tid = threadIdx.x;
    const float* esb = es + b * NN;
    const unsigned* mrow = g_maskbits + ((long)b * NN + t) * NW;
    for (int i = tid; i < NN; i += 256) ses[i] = esb[i];
    if (tid < NW) smask[tid] = mrow[tid];
    __syncthreads();

    float edv = ed[b * NN + t];
    float mx = -1e30f;
    for (int s = tid; s < NN; s += 256)
        if ((smask[s >> 5] >> (s & 31)) & 1u) mx = fmaxf(mx, ses[s]);
    red[tid] = mx; __syncthreads();
    for (int o = 128; o; o >>= 1) {
        if (tid < o) red[tid] = fmaxf(red[tid], red[tid + o]);
        __syncthreads();
    }
    float mlog = lrelu(edv + red[0]);
    __syncthreads();

    float sum = 0.f;
    for (int s = tid; s < NN; s += 256)
        if ((smask[s >> 5] >> (s & 31)) & 1u)
            sum += expf(lrelu(edv + ses[s]) - mlog);
    red[tid] = sum; __syncthreads();
    for (int o = 128; o; o >>= 1) {
        if (tid < o) red[tid] += red[tid + o];
        __syncthreads();
    }
    float inv = 1.f / red[0];

    float* arow = g_alpha + ((long)b * NN + t) * NN;
    for (int s = tid; s < NN; s += 256) {
        float v = 0.f;
        if ((smask[s >> 5] >> (s & 31)) & 1u)
            v = expf(lrelu(edv + ses[s]) - mlog) * inv;
        arow[s] = v;
    }
}

// ---------------- host orchestration --------------------------------------------
static void gemm(const float* A, const float* W, const float* bias,
                 const float* res, const float* rowscale, float* C,
                 int M, int K, int Nn, int relu, int batch,
                 long sA, long sB, long sC) {
    dim3 grid(Nn / BN, M / BM, batch), block(16, 16);
    gemm_kernel<<<grid, block>>>(A, W, bias, res, rowscale, C, M, K, Nn, relu, sA, sB, sC);
}

extern "C" void kernel_launch(void* const* d_in, const int* in_sizes, int n_in,
                              void* d_out, int out_size) {
    const int*   adj       = (const int*)d_in[0];
    const float* arrivals  = (const float*)d_in[1];
    const float* departs   = (const float*)d_in[2];
    const float* hard      = (const float*)d_in[3];
    const float* active    = (const float*)d_in[4];
    const float* timestep  = (const float*)d_in[5];
    const float* total     = (const float*)d_in[6];
    const float* emb_W1 = (const float*)d_in[7],  *emb_b1 = (const float*)d_in[8];
    const float* emb_W2 = (const float*)d_in[9],  *emb_b2 = (const float*)d_in[10];
    const float* gW0 = (const float*)d_in[11], *ga0s = (const float*)d_in[12],
               * ga0d = (const float*)d_in[13], *gb0 = (const float*)d_in[14];
    const float* gW1 = (const float*)d_in[15], *ga1s = (const float*)d_in[16],
               * ga1d = (const float*)d_in[17], *gb1 = (const float*)d_in[18];
    const float* gW2 = (const float*)d_in[19], *ga2s = (const float*)d_in[20],
               * ga2d = (const float*)d_in[21], *gb2 = (const float*)d_in[22];
    const float* fW1 = (const float*)d_in[23], *fb1 = (const float*)d_in[24];
    const float* fW2 = (const float*)d_in[25], *fb2 = (const float*)d_in[26];
    float* out = (float*)d_out;

    float *px, *pt, *ph, *pg2, *phw, *pes, *ped, *palpha;
    cudaGetSymbolAddress((void**)&px, g_x);
    cudaGetSymbolAddress((void**)&pt, g_t);
    cudaGetSymbolAddress((void**)&ph, g_h);
    cudaGetSymbolAddress((void**)&pg2, g_g2);
    cudaGetSymbolAddress((void**)&phw, g_hw);
    cudaGetSymbolAddress((void**)&pes, g_es);
    cudaGetSymbolAddress((void**)&ped, g_ed);
    cudaGetSymbolAddress((void**)&palpha, g_alpha);

    // 1. transposed+packed mask (shared by all GAT layers)
    {
        dim3 grid(NN / 32, NN / 32, BB), block(32, 32);
        mask_kernel<<<grid, block>>>(adj);
    }
    // 2. embedding: feats@W1+b1 -> g_t ; g_t@W2+b2 -> g_x
    embed1_kernel<<<MM, HH>>>(arrivals, departs, hard, timestep, total, emb_W1, emb_b1, pt);
    gemm(pt, emb_W2, emb_b2, nullptr, nullptr, px, MM, HH, HH, 0, 1, 0, 0, 0);

    const long sAlpha = (long)NN * NN;
    // --- GAT layer 0: in g_x (512) -> g_h (1024), relu
    gemm(px, gW0, nullptr, nullptr, nullptr, phw, MM, HH, H2, 0, 1, 0, 0, 0);
    ev_kernel<<<MM / 8, 256>>>(phw, ga0s, ga0d, pes, ped, H2);
    { dim3 grid(NN, BB); alpha_kernel<<<grid, 256>>>(pes, ped); }
    gemm(palpha, phw, gb0, nullptr, nullptr, ph, NN, NN, H2, 1, BB,
         sAlpha, (long)NN * H2, (long)NN * H2);

    // --- GAT layer 1: g_h (1024) -> g_g2 (1024), relu
    gemm(ph, gW1, nullptr, nullptr, nullptr, phw, MM, H2, H2, 0, 1, 0, 0, 0);
    ev_kernel<<<MM / 8, 256>>>(phw, ga1s, ga1d, pes, ped, H2);
    { dim3 grid(NN, BB); alpha_kernel<<<grid, 256>>>(pes, ped); }
    gemm(palpha, phw, gb1, nullptr, nullptr, pg2, NN, NN, H2, 1, BB,
         sAlpha, (long)NN * H2, (long)NN * H2);

    // --- GAT layer 2: g_g2 (1024) -> 512, no relu, + residual g_x  -> g_t
    gemm(pg2, gW2, nullptr, nullptr, nullptr, phw, MM, H2, HH, 0, 1, 0, 0, 0);
    ev_kernel<<<MM / 8, 256>>>(phw, ga2s, ga2d, pes, ped, HH);
    { dim3 grid(NN, BB); alpha_kernel<<<grid, 256>>>(pes, ped); }
    gemm(palpha, phw, gb2, px, nullptr, pt, NN, NN, HH, 0, BB,
         sAlpha, (long)NN * HH, (long)NN * HH);

    // --- FF residuals
    // x2 = g_t + relu(g_t@fW1+fb1) -> g_h (512-wide slice)
    gemm(pt, fW1, fb1, pt, nullptr, ph, MM, HH, HH, 1, 1, 0, 0, 0);
    // out = (g_h + relu(g_h@fW2+fb2)) * active
    gemm(ph, fW2, fb2, ph, active, out, MM, HH, HH, 1, 1, 0, 0, 0);
}

// round 5
// speedup vs baseline: 2.2106x; 2.2106x over previous
#include <cuda_runtime.h>
#include <cuda_bf16.h>
#include <cstdint>
#include <math.h>

// ---------------- problem constants ----------------
#define BB 8
#define NN 2048
#define HH 512
#define H2 1024
#define MM (BB * NN)          // 16384 rows total
#define NW (NN / 32)

// ---------------- GEMM tile config ----------------
#define GM 128
#define GN 128
#define GK 32
#define GT 256
#define SLAB 4096                      // floats per staged operand slab
#define SMEM_BYTES (4 * SLAB * 4)      // A0 A1 B0 B1 = 64 KB

// ---------------- static device scratch ----------------
__device__ float    g_x[(long)MM * HH];
__device__ float    g_t[(long)MM * HH];
__device__ float    g_h[(long)MM * H2];
__device__ float    g_hwT[(long)H2 * MM];            // transposed hw: [F][16384]
__device__ float    g_alpha[(long)BB * NN * NN];     // unnormalized exp
__device__ float    g_es[MM], g_ed[MM], g_inv[MM];
__device__ unsigned g_maskbits[(long)BB * NN * NW];
__device__ float    g_embW2T[HH * HH];
__device__ float    g_W0T[H2 * HH];
__device__ float    g_W1T[H2 * H2];
__device__ float    g_W2T[HH * H2];
__device__ float    g_fW1T[HH * HH];
__device__ float    g_fW2T[HH * HH];

__device__ __forceinline__ float tf32r(float x) {
    float y; asm("cvt.rna.tf32.f32 %0, %1;" : "=f"(y) : "f"(x)); return y;
}

// mma.sync m16n8k8 tf32 (baseline PTX, lowered to HMMA on sm_103)
__device__ __forceinline__ void mma8(float* c, const uint32_t* a, const uint32_t* b) {
    asm volatile(
        "mma.sync.aligned.m16n8k8.row.col.f32.tf32.tf32.f32 "
        "{%0,%1,%2,%3}, {%4,%5,%6,%7}, {%8,%9}, {%0,%1,%2,%3};"
        : "+f"(c[0]), "+f"(c[1]), "+f"(c[2]), "+f"(c[3])
        : "r"(a[0]), "r"(a[1]), "r"(a[2]), "r"(a[3]), "r"(b[0]), "r"(b[1]));
}

// ---------------- staging: global -> fragment-ordered SMEM ----------------------
// A slab [128 rows x 32 k]:
//   element (row, col): tile = (col>>3)*8 + (row>>4)   (128 floats per tile)
//   within tile: pos = gid*16 + tig*4 + half + 2*chalf
//   gid=row&7, half=(row>>3)&1, tig=col&3, chalf=(col>>2)&1
__device__ __forceinline__ void ldgA(const float* __restrict__ Ag, long ld,
                                     float4 v[4], int tid) {
    #pragma unroll
    for (int i = 0; i < 4; i++) {
        int e = tid + i * 256;
        int row = e >> 3, c4 = (e & 7) << 2;
        v[i] = *(const float4*)(Ag + (long)row * ld + c4);
    }
}
__device__ __forceinline__ void stsA(float* __restrict__ sA, const float4 v[4], int tid) {
    #pragma unroll
    for (int i = 0; i < 4; i++) {
        int e = tid + i * 256;
        int row = e >> 3, c4 = (e & 7) << 2;
        int kk = c4 >> 3, chalf = (c4 >> 2) & 1;
        int mt = row >> 4, gid = row & 7, half = (row >> 3) & 1;
        int base = (((kk << 3) + mt) << 7) + (gid << 4) + half + (chalf << 1);
        // consecutive columns => tig = 0..3 => offset tig*4
        sA[base]      = tf32r(v[i].x);
        sA[base + 4]  = tf32r(v[i].y);
        sA[base + 8]  = tf32r(v[i].z);
        sA[base + 12] = tf32r(v[i].w);
    }
}
// B slab [128 n x 32 k]:
//   element (n, k): tile = (k>>3)*16 + (n>>3)   (64 floats per tile)
//   within tile: pos = gid*8 + tig*2 + reg ; gid=n&7, tig=k&3, reg=(k>>2)&1
__device__ __forceinline__ void ldgB(const float* __restrict__ Bg, long ld,
                                     float4 v[4], int tid) {
    #pragma unroll
    for (int i = 0; i < 4; i++) {
        int e = tid + i * 256;
        int n = e >> 3, k4 = (e & 7) << 2;
        v[i] = *(const float4*)(Bg + (long)n * ld + k4);
    }
}
__device__ __forceinline__ void stsB(float* __restrict__ sB, const float4 v[4], int tid) {
    #pragma unroll
    for (int i = 0; i < 4; i++) {
        int e = tid + i * 256;
        int n = e >> 3, k4 = (e & 7) << 2;
        int nt = n >> 3, gid = n & 7;
        int kk = k4 >> 3, reg = (k4 >> 2) & 1;
        int base = (((kk << 4) + nt) << 6) + (gid << 3) + reg;
        // consecutive k => tig = 0..3 => offset tig*2
        sB[base]     = tf32r(v[i].x);
        sB[base + 2] = tf32r(v[i].y);
        sB[base + 4] = tf32r(v[i].z);
        sB[base + 6] = tf32r(v[i].w);
    }
}

// ---------------- mma.sync tf32 GEMM --------------------------------------------
// C[M,N] = epi(A[M,K] @ BT[N,K]^T); BT row-major [N,K].
// epi: v = acc*prescale[r] + bias[c]; relu; += res; *= postscale[r];
// optional transC; optional es/ed = Σ v*asrc / Σ v*adst (atomic per row).
__global__ void __launch_bounds__(GT)
tc_gemm(const float* __restrict__ A, const float* __restrict__ BT,
        const float* __restrict__ bias, const float* __restrict__ res,
        const float* __restrict__ prescale, const float* __restrict__ postscale,
        const float* __restrict__ asrc, const float* __restrict__ adst,
        float* __restrict__ es, float* __restrict__ ed,
        float* __restrict__ C, int M, int K, int N, int ldbt,
        int relu, int transC, int ldct,
        long sA_, long sB_, long sC_, int rowOff) {
    extern __shared__ float smem[];
    int tid = threadIdx.x, lane = tid & 31, w = tid >> 5;
    int wm = w & 3, wn = w >> 2;              // 4 warps along M, 2 along N
    int gid = lane >> 2, tig = lane & 3;
    int bz = blockIdx.z;
    A += bz * sA_; BT += bz * sB_; C += bz * sC_;
    if (res) res += bz * sC_;
    int ro = bz * rowOff;
    if (prescale) prescale += ro;
    if (postscale) postscale += ro;
    if (es) { es += ro; ed += ro; }

    int m0 = blockIdx.y * GM, n0 = blockIdx.x * GN;
    const float* Ab = A + (long)m0 * K;
    const float* Bb = BT + (long)n0 * ldbt;
    int nc = K / GK;

    float acc[2][8][4];
    #pragma unroll
    for (int i = 0; i < 2; i++)
        #pragma unroll
        for (int j = 0; j < 8; j++)
            #pragma unroll
            for (int q = 0; q < 4; q++) acc[i][j][q] = 0.f;

    // prologue: slab 0 -> buf 0
    {
        float4 va[4], vb[4];
        ldgA(Ab, K, va, tid); ldgB(Bb, ldbt, vb, tid);
        stsA(smem, va, tid);  stsB(smem + 2 * SLAB, vb, tid);
    }
    __syncthreads();

    for (int c = 0; c < nc; c++) {
        float4 va[4], vb[4];
        if (c + 1 < nc) {
            ldgA(Ab + (c + 1) * GK, K, va, tid);
            ldgB(Bb + (c + 1) * GK, ldbt, vb, tid);
        }
        const float* cA = smem + (c & 1) * SLAB;
        const float* cB = smem + 2 * SLAB + (c & 1) * SLAB;
        #pragma unroll
        for (int kk = 0; kk < 4; kk++) {
            uint32_t af[2][4];
            #pragma unroll
            for (int mt = 0; mt < 2; mt++) {
                float4 t = *(const float4*)(cA + ((((kk << 3) + wm * 2 + mt) << 5) + lane) * 4);
                af[mt][0] = __float_as_uint(t.x); af[mt][1] = __float_as_uint(t.y);
                af[mt][2] = __float_as_uint(t.z); af[mt][3] = __float_as_uint(t.w);
            }
            #pragma unroll
            for (int nt = 0; nt < 8; nt++) {
                float2 t = *(const float2*)(cB + ((((kk << 4) + wn * 8 + nt) << 5) + lane) * 2);
                uint32_t bf[2] = { __float_as_uint(t.x), __float_as_uint(t.y) };
                mma8(acc[0][nt], af[0], bf);
                mma8(acc[1][nt], af[1], bf);
            }
        }
        if (c + 1 < nc) {
            int nb = (c + 1) & 1;
            stsA(smem + nb * SLAB, va, tid);
            stsB(smem + 2 * SLAB + nb * SLAB, vb, tid);
        }
        __syncthreads();
    }

    // epilogue
    #pragma unroll
    for (int mt = 0; mt < 2; mt++) {
        #pragma unroll
        for (int half = 0; half < 2; half++) {
            int r = m0 + wm * 32 + mt * 16 + half * 8 + gid;
            float presv = prescale ? prescale[r] : 1.f;
            float postv = postscale ? postscale[r] : 1.f;
            float se = 0.f, sd = 0.f;
            #pragma unroll
            for (int nt = 0; nt < 8; nt++) {
                int cidx = n0 + wn * 64 + nt * 8 + tig * 2;
                float v0 = acc[mt][nt][half * 2 + 0] * presv;
                float v1 = acc[mt][nt][half * 2 + 1] * presv;
                if (bias) { v0 += bias[cidx]; v1 += bias[cidx + 1]; }
                if (relu) { v0 = fmaxf(v0, 0.f); v1 = fmaxf(v1, 0.f); }
                if (res) {
                    float2 rv = *(const float2*)(res + (long)r * N + cidx);
                    v0 += rv.x; v1 += rv.y;
                }
                v0 *= postv; v1 *= postv;
                if (asrc) {
                    se += v0 * asrc[cidx] + v1 * asrc[cidx + 1];
                    sd += v0 * adst[cidx] + v1 * adst[cidx + 1];
                }
                if (transC) {
                    C[(long)cidx * ldct + r] = v0;
                    C[(long)(cidx + 1) * ldct + r] = v1;
                } else {
                    *(float2*)(C + (long)r * N + cidx) = make_float2(v0, v1);
                }
            }
            if (es) { atomicAdd(es + r, se); atomicAdd(ed + r, sd); }
        }
    }
}

// ---------------- mask transpose + bitpack --------------------------------------
__global__ void mask_kernel(const int* __restrict__ adj) {
    __shared__ int tile[32][33];
    int b = blockIdx.z;
    int t0 = blockIdx.x * 32, s0 = blockIdx.y * 32;
    tile[threadIdx.y][threadIdx.x] =
        adj[((long)b * NN + (s0 + threadIdx.y)) * NN + t0 + threadIdx.x];
    __syncthreads();
    if (threadIdx.y == 0) {
        int t = t0 + threadIdx.x;
        unsigned w = 0u;
        #pragma unroll
        for (int i = 0; i < 32; i++) {
            int s = s0 + i;
            if (tile[i][threadIdx.x] != 0 || s == t) w |= (1u << i);
        }
        g_maskbits[((long)b * NN + t) * NW + (s0 >> 5)] = w;
    }
}

// ---------------- features + first embedding linear (K=6) -----------------------
__global__ void embed1_kernel(const float* __restrict__ arrivals,
                              const float* __restrict__ departures,
                              const float* __restrict__ hard,
                              const float* __restrict__ timestep,
                              const float* __restrict__ total,
                              const float* __restrict__ W1,
                              const float* __restrict__ b1,
                              float* __restrict__ out) {
    int m = blockIdx.x, f = threadIdx.x;
    int b = m / NN;
    float ts = timestep[b], tot = total[b];
    float arr = arrivals[m], dep = departures[m];
    float fe[6];
    fe[0] = (ts - arr) / (dep - arr);
    fe[1] = ts / tot;
    fe[2] = fmodf(fe[1], 2.f); fe[3] = fmodf(fe[1], 4.f); fe[4] = fmodf(fe[1], 7.f);
    fe[5] = hard[m];
    float acc = b1[f];
    #pragma unroll
    for (int k = 0; k < 6; k++) acc += fe[k] * W1[k * HH + f];
    out[(long)m * HH + f] = acc;
}

// ---------------- masked softmax -> unnormalized exp + 1/rowsum -----------------
__device__ __forceinline__ float lrelu(float x) { return x > 0.f ? x : 0.2f * x; }

__global__ void alpha_kernel(const float* __restrict__ es,
                             const float* __restrict__ ed,
                             float* __restrict__ inv) {
    __shared__ float    ses[NN];
    __shared__ unsigned smask[NW];
    __shared__ float    red[256];
    int t = blockIdx.x, b = blockIdx.y, tid = threadIdx.x;
    const float* esb = es + b * NN;
    const unsigned* mrow = g_maskbits + ((long)b * NN + t) * NW;
    for (int i = tid; i < NN; i += 256) ses[i] = esb[i];
    if (tid < NW) smask[tid] = mrow[tid];
    __syncthreads();

    float edv = ed[b * NN + t];
    float mx = -1e30f;
    for (int s = tid; s < NN; s += 256)
        if ((smask[s >> 5] >> (s & 31)) & 1u) mx = fmaxf(mx, ses[s]);
    red[tid] = mx; __syncthreads();
    for (int o = 128; o; o >>= 1) {
        if (tid < o) red[tid] = fmaxf(red[tid], red[tid + o]);
        __syncthreads();
    }
    float mlog = lrelu(edv + red[0]);
    __syncthreads();

    float* arow = g_alpha + ((long)b * NN + t) * NN;
    float sum = 0.f;
    for (int s = tid; s < NN; s += 256) {
        float v = 0.f;
        if ((smask[s >> 5] >> (s & 31)) & 1u)
            v = __expf(lrelu(edv + ses[s]) - mlog);
        arow[s] = v;
        sum += v;
    }
    red[tid] = sum; __syncthreads();
    for (int o = 128; o; o >>= 1) {
        if (tid < o) red[tid] += red[tid + o];
        __syncthreads();
    }
    if (tid == 0) inv[b * NN + t] = 1.f / red[0];
}

// ---------------- weight transpose [K,N] -> [N,K] -------------------------------
__global__ void transpose_kernel(const float* __restrict__ in, float* __restrict__ out,
                                 int K, int N) {
    __shared__ float t[32][33];
    int n0 = blockIdx.x * 32, k0 = blockIdx.y * 32;
    int x = threadIdx.x;
    for (int y = threadIdx.y; y < 32; y += 8)
        t[y][x] = in[(long)(k0 + y) * N + n0 + x];
    __syncthreads();
    for (int y = threadIdx.y; y < 32; y += 8)
        out[(long)(n0 + y) * K + k0 + x] = t[x][y];
}

// ---------------- host orchestration --------------------------------------------
static void gemmTC(const float* A, const float* BT, const float* bias, const float* res,
                   const float* presc, const float* postsc,
                   const float* asrc, const float* adst, float* es, float* ed,
                   float* C, int M, int K, int N, int ldbt, int relu,
                   int transC, int ldct, long sA, long sB, long sC, int rowOff, int batch) {
    dim3 grid(N / GN, M / GM, batch);
    tc_gemm<<<grid, GT, SMEM_BYTES>>>(A, BT, bias, res, presc, postsc, asrc, adst,
                                      es, ed, C, M, K, N, ldbt, relu, transC, ldct,
                                      sA, sB, sC, rowOff);
}

extern "C" void kernel_launch(void* const* d_in, const int* in_sizes, int n_in,
                              void* d_out, int out_size) {
    const int*   adj      = (const int*)d_in[0];
    const float* arrivals = (const float*)d_in[1];
    const float* departs  = (const float*)d_in[2];
    const float* hard     = (const float*)d_in[3];
    const float* active   = (const float*)d_in[4];
    const float* timestep = (const float*)d_in[5];
    const float* total    = (const float*)d_in[6];
    const float* emb_W1 = (const float*)d_in[7],  *emb_b1 = (const float*)d_in[8];
    const float* emb_W2 = (const float*)d_in[9],  *emb_b2 = (const float*)d_in[10];
    const float* gW0 = (const float*)d_in[11], *ga0s = (const float*)d_in[12],
               * ga0d = (const float*)d_in[13], *gb0 = (const float*)d_in[14];
    const float* gW1 = (const float*)d_in[15], *ga1s = (const float*)d_in[16],
               * ga1d = (const float*)d_in[17], *gb1 = (const float*)d_in[18];
    const float* gW2 = (const float*)d_in[19], *ga2s = (const float*)d_in[20],
               * ga2d = (const float*)d_in[21], *gb2 = (const float*)d_in[22];
    const float* fW1 = (const float*)d_in[23], *fb1 = (const float*)d_in[24];
    const float* fW2 = (const float*)d_in[25], *fb2 = (const float*)d_in[26];
    float* out = (float*)d_out;

    cudaFuncSetAttribute(tc_gemm, cudaFuncAttributeMaxDynamicSharedMemorySize, SMEM_BYTES);

    float *px, *pt, *ph, *phwT, *palpha, *pes, *ped, *pinv;
    float *pW2T, *pW0T, *pW1T, *pgW2T, *pf1T, *pf2T;
    cudaGetSymbolAddress((void**)&px, g_x);
    cudaGetSymbolAddress((void**)&pt, g_t);
    cudaGetSymbolAddress((void**)&ph, g_h);
    cudaGetSymbolAddress((void**)&phwT, g_hwT);
    cudaGetSymbolAddress((void**)&palpha, g_alpha);
    cudaGetSymbolAddress((void**)&pes, g_es);
    cudaGetSymbolAddress((void**)&ped, g_ed);
    cudaGetSymbolAddress((void**)&pinv, g_inv);
    cudaGetSymbolAddress((void**)&pW2T, g_embW2T);
    cudaGetSymbolAddress((void**)&pW0T, g_W0T);
    cudaGetSymbolAddress((void**)&pW1T, g_W1T);
    cudaGetSymbolAddress((void**)&pgW2T, g_W2T);
    cudaGetSymbolAddress((void**)&pf1T, g_fW1T);
    cudaGetSymbolAddress((void**)&pf2T, g_fW2T);

    // weight transposes ([K,N] -> [N,K])
    dim3 tb(32, 8);
    transpose_kernel<<<dim3(HH/32, HH/32), tb>>>(emb_W2, pW2T, HH, HH);
    transpose_kernel<<<dim3(H2/32, HH/32), tb>>>(gW0, pW0T, HH, H2);
    transpose_kernel<<<dim3(H2/32, H2/32), tb>>>(gW1, pW1T, H2, H2);
    transpose_kernel<<<dim3(HH/32, H2/32), tb>>>(gW2, pgW2T, H2, HH);
    transpose_kernel<<<dim3(HH/32, HH/32), tb>>>(fW1, pf1T, HH, HH);
    transpose_kernel<<<dim3(HH/32, HH/32), tb>>>(fW2, pf2T, HH, HH);

    // mask
    { dim3 grid(NN/32, NN/32, BB), blk(32, 32); mask_kernel<<<grid, blk>>>(adj); }

    // embedding
    embed1_kernel<<<MM, HH>>>(arrivals, departs, hard, timestep, total, emb_W1, emb_b1, pt);
    gemmTC(pt, pW2T, emb_b2, nullptr, nullptr, nullptr, nullptr, nullptr, nullptr, nullptr,
           px, MM, HH, HH, HH, 0, 0, 0, 0, 0, 0, 0, 1);

    const long sAl = (long)NN * NN;
    struct Layer {
        const float *Ain, *WT, *as, *ad, *bias; int Kf, Nf; float* aggC; const float* resid; int relu;
    } L[3] = {
        { px, pW0T,  ga0s, ga0d, gb0, HH, H2, ph, nullptr, 1 },
        { ph, pW1T,  ga1s, ga1d, gb1, H2, H2, ph, nullptr, 1 },
        { ph, pgW2T, ga2s, ga2d, gb2, H2, HH, pt, px,      0 },
    };
    for (int l = 0; l < 3; l++) {
        cudaMemsetAsync(pes, 0, MM * sizeof(float));
        cudaMemsetAsync(ped, 0, MM * sizeof(float));
        // hw = A @ W, written transposed to g_hwT; es/ed accumulated in epilogue
        gemmTC(L[l].Ain, L[l].WT, nullptr, nullptr, nullptr, nullptr,
               L[l].as, L[l].ad, pes, ped,
               phwT, MM, L[l].Kf, L[l].Nf, L[l].Kf, 0, 1, MM, 0, 0, 0, 0, 1);
        // masked softmax -> unnormalized alpha + inv rowsum
        { dim3 grid(NN, BB); alpha_kernel<<<grid, 256>>>(pes, ped, pinv); }
        // aggregation: (U @ hw) * inv + bias [+relu] [+residual]
        gemmTC(palpha, phwT, L[l].bias, L[l].resid, pinv, nullptr,
               nullptr, nullptr, nullptr, nullptr,
               L[l].aggC, NN, NN, L[l].Nf, MM, L[l].relu, 0, 0,
               sAl, (long)NN, (long)NN * L[l].Nf, NN, BB);
    }

    // FF residuals: x += relu(x@W+b) twice; final * active
    gemmTC(pt, pf1T, fb1, pt, nullptr, nullptr, nullptr, nullptr, nullptr, nullptr,
           ph, MM, HH, HH, HH, 1, 0, 0, 0, 0, 0, 0, 1);
    gemmTC(ph, pf2T, fb2, ph, nullptr, active, nullptr, nullptr, nullptr, nullptr,
           out, MM, HH, HH, HH, 1, 0, 0, 0, 0, 0, 0, 1);
}

// round 7
// speedup vs baseline: 2.2142x; 1.0017x over previous
#include <cuda_runtime.h>
#include <cuda_bf16.h>
#include <cstdint>
#include <math.h>

// ---------------- problem constants ----------------
#define BB 8
#define NN 2048
#define HH 512
#define H2 1024
#define MM (BB * NN)          // 16384 rows total
#define NW (NN / 32)

// ---------------- GEMM tile config ----------------
#define GM 128
#define GN 128
#define GK 32
#define GT 256
#define SLAB 4096                      // floats per staged operand slab
#define SMEM_BYTES (4 * SLAB * 4)      // A0 A1 B0 B1 = 64 KB

// ---------------- static device scratch ----------------
__device__ float    g_x[(long)MM * HH];
__device__ float    g_t[(long)MM * HH];
__device__ float    g_h[(long)MM * H2];
__device__ float    g_hwT[(long)H2 * MM];            // transposed hw: [F][16384]
__device__ float    g_alpha[(long)BB * NN * NN];     // unnormalized exp
__device__ float    g_esd[2 * MM];                   // es | ed fused
__device__ float    g_inv[MM];
__device__ unsigned g_maskbits[(long)BB * NN * NW];
__device__ float    g_embW2T[HH * HH];
__device__ float    g_W0T[H2 * HH];
__device__ float    g_W1T[H2 * H2];
__device__ float    g_W2T[HH * H2];
__device__ float    g_fW1T[HH * HH];
__device__ float    g_fW2T[HH * HH];

__device__ __forceinline__ float tf32r(float x) {
    float y; asm("cvt.rna.tf32.f32 %0, %1;" : "=f"(y) : "f"(x)); return y;
}

// mma.sync m16n8k8 tf32 (baseline PTX, lowered to HMMA on sm_103)
__device__ __forceinline__ void mma8(float* c, const uint32_t* a, const uint32_t* b) {
    asm volatile(
        "mma.sync.aligned.m16n8k8.row.col.f32.tf32.tf32.f32 "
        "{%0,%1,%2,%3}, {%4,%5,%6,%7}, {%8,%9}, {%0,%1,%2,%3};"
        : "+f"(c[0]), "+f"(c[1]), "+f"(c[2]), "+f"(c[3])
        : "r"(a[0]), "r"(a[1]), "r"(a[2]), "r"(a[3]), "r"(b[0]), "r"(b[1]));
}

// ---------------- staging: global -> fragment-ordered SMEM ----------------------
__device__ __forceinline__ void ldgA(const float* __restrict__ Ag, long ld,
                                     float4 v[4], int tid) {
    #pragma unroll
    for (int i = 0; i < 4; i++) {
        int e = tid + i * 256;
        int row = e >> 3, c4 = (e & 7) << 2;
        v[i] = *(const float4*)(Ag + (long)row * ld + c4);
    }
}
__device__ __forceinline__ void stsA(float* __restrict__ sA, const float4 v[4], int tid) {
    #pragma unroll
    for (int i = 0; i < 4; i++) {
        int e = tid + i * 256;
        int row = e >> 3, c4 = (e & 7) << 2;
        int kk = c4 >> 3, chalf = (c4 >> 2) & 1;
        int mt = row >> 4, gid = row & 7, half = (row >> 3) & 1;
        int base = (((kk << 3) + mt) << 7) + (gid << 4) + half + (chalf << 1);
        sA[base]      = tf32r(v[i].x);
        sA[base + 4]  = tf32r(v[i].y);
        sA[base + 8]  = tf32r(v[i].z);
        sA[base + 12] = tf32r(v[i].w);
    }
}
__device__ __forceinline__ void ldgB(const float* __restrict__ Bg, long ld,
                                     float4 v[4], int tid) {
    #pragma unroll
    for (int i = 0; i < 4; i++) {
        int e = tid + i * 256;
        int n = e >> 3, k4 = (e & 7) << 2;
        v[i] = *(const float4*)(Bg + (long)n * ld + k4);
    }
}
__device__ __forceinline__ void stsB(float* __restrict__ sB, const float4 v[4], int tid) {
    #pragma unroll
    for (int i = 0; i < 4; i++) {
        int e = tid + i * 256;
        int n = e >> 3, k4 = (e & 7) << 2;
        int nt = n >> 3, gid = n & 7;
        int kk = k4 >> 3, reg = (k4 >> 2) & 1;
        int base = (((kk << 4) + nt) << 6) + (gid << 3) + reg;
        sB[base]     = tf32r(v[i].x);
        sB[base + 2] = tf32r(v[i].y);
        sB[base + 4] = tf32r(v[i].z);
        sB[base + 6] = tf32r(v[i].w);
    }
}

// ---------------- mma.sync tf32 GEMM --------------------------------------------
__global__ void __launch_bounds__(GT)
tc_gemm(const float* __restrict__ A, const float* __restrict__ BT,
        const float* __restrict__ bias, const float* __restrict__ res,
        const float* __restrict__ prescale, const float* __restrict__ postscale,
        const float* __restrict__ asrc, const float* __restrict__ adst,
        float* __restrict__ es, float* __restrict__ ed,
        float* __restrict__ C, int M, int K, int N, int ldbt,
        int relu, int transC, int ldct,
        long sA_, long sB_, long sC_, int rowOff) {
    extern __shared__ float smem[];
    int tid = threadIdx.x, lane = tid & 31, w = tid >> 5;
    int wm = w & 3, wn = w >> 2;              // 4 warps along M, 2 along N
    int gid = lane >> 2, tig = lane & 3;
    int bz = blockIdx.z;
    A += bz * sA_; BT += bz * sB_; C += bz * sC_;
    if (res) res += bz * sC_;
    int ro = bz * rowOff;
    if (prescale) prescale += ro;
    if (postscale) postscale += ro;
    if (es) { es += ro; ed += ro; }

    int m0 = blockIdx.y * GM, n0 = blockIdx.x * GN;
    const float* Ab = A + (long)m0 * K;
    const float* Bb = BT + (long)n0 * ldbt;
    int nc = K / GK;

    float acc[2][8][4];
    #pragma unroll
    for (int i = 0; i < 2; i++)
        #pragma unroll
        for (int j = 0; j < 8; j++)
            #pragma unroll
            for (int q = 0; q < 4; q++) acc[i][j][q] = 0.f;

    {
        float4 va[4], vb[4];
        ldgA(Ab, K, va, tid); ldgB(Bb, ldbt, vb, tid);
        stsA(smem, va, tid);  stsB(smem + 2 * SLAB, vb, tid);
    }
    __syncthreads();

    for (int c = 0; c < nc; c++) {
        float4 va[4], vb[4];
        if (c + 1 < nc) {
            ldgA(Ab + (c + 1) * GK, K, va, tid);
            ldgB(Bb + (c + 1) * GK, ldbt, vb, tid);
        }
        const float* cA = smem + (c & 1) * SLAB;
        const float* cB = smem + 2 * SLAB + (c & 1) * SLAB;
        #pragma unroll
        for (int kk = 0; kk < 4; kk++) {
            uint32_t af[2][4];
            #pragma unroll
            for (int mt = 0; mt < 2; mt++) {
                float4 t = *(const float4*)(cA + ((((kk << 3) + wm * 2 + mt) << 5) + lane) * 4);
                af[mt][0] = __float_as_uint(t.x); af[mt][1] = __float_as_uint(t.y);
                af[mt][2] = __float_as_uint(t.z); af[mt][3] = __float_as_uint(t.w);
            }
            #pragma unroll
            for (int nt = 0; nt < 8; nt++) {
                float2 t = *(const float2*)(cB + ((((kk << 4) + wn * 8 + nt) << 5) + lane) * 2);
                uint32_t bf[2] = { __float_as_uint(t.x), __float_as_uint(t.y) };
                mma8(acc[0][nt], af[0], bf);
                mma8(acc[1][nt], af[1], bf);
            }
        }
        if (c + 1 < nc) {
            int nb = (c + 1) & 1;
            stsA(smem + nb * SLAB, va, tid);
            stsB(smem + 2 * SLAB + nb * SLAB, vb, tid);
        }
        __syncthreads();
    }

    // epilogue
    #pragma unroll
    for (int mt = 0; mt < 2; mt++) {
        #pragma unroll
        for (int half = 0; half < 2; half++) {
            int r = m0 + wm * 32 + mt * 16 + half * 8 + gid;
            float presv = prescale ? prescale[r] : 1.f;
            float postv = postscale ? postscale[r] : 1.f;
            float se = 0.f, sd = 0.f;
            #pragma unroll
            for (int nt = 0; nt < 8; nt++) {
                int cidx = n0 + wn * 64 + nt * 8 + tig * 2;
                float v0 = acc[mt][nt][half * 2 + 0] * presv;
                float v1 = acc[mt][nt][half * 2 + 1] * presv;
                if (bias) { v0 += bias[cidx]; v1 += bias[cidx + 1]; }
                if (relu) { v0 = fmaxf(v0, 0.f); v1 = fmaxf(v1, 0.f); }
                if (res) {
                    float2 rv = *(const float2*)(res + (long)r * N + cidx);
                    v0 += rv.x; v1 += rv.y;
                }
                v0 *= postv; v1 *= postv;
                if (asrc) {
                    se += v0 * asrc[cidx] + v1 * asrc[cidx + 1];
                    sd += v0 * adst[cidx] + v1 * adst[cidx + 1];
                }
                if (transC) {
                    C[(long)cidx * ldct + r] = v0;
                    C[(long)(cidx + 1) * ldct + r] = v1;
                } else {
                    *(float2*)(C + (long)r * N + cidx) = make_float2(v0, v1);
                }
            }
            if (es) { atomicAdd(es + r, se); atomicAdd(ed + r, sd); }
        }
    }
}

// ---------------- mask transpose + bitpack --------------------------------------
__global__ void mask_kernel(const int* __restrict__ adj) {
    __shared__ int tile[32][33];
    int b = blockIdx.z;
    int t0 = blockIdx.x * 32, s0 = blockIdx.y * 32;
    tile[threadIdx.y][threadIdx.x] =
        adj[((long)b * NN + (s0 + threadIdx.y)) * NN + t0 + threadIdx.x];
    __syncthreads();
    if (threadIdx.y == 0) {
        int t = t0 + threadIdx.x;
        unsigned w = 0u;
        #pragma unroll
        for (int i = 0; i < 32; i++) {
            int s = s0 + i;
            if (tile[i][threadIdx.x] != 0 || s == t) w |= (1u << i);
        }
        g_maskbits[((long)b * NN + t) * NW + (s0 >> 5)] = w;
    }
}

// ---------------- features + first embedding linear (K=6) -----------------------
__global__ void embed1_kernel(const float* __restrict__ arrivals,
                              const float* __restrict__ departures,
                              const float* __restrict__ hard,
                              const float* __restrict__ timestep,
                              const float* __restrict__ total,
                              const float* __restrict__ W1,
                              const float* __restrict__ b1,
                              float* __restrict__ out) {
    int m = blockIdx.x, f = threadIdx.x;
    int b = m / NN;
    float ts = timestep[b], tot = total[b];
    float arr = arrivals[m], dep = departures[m];
    float fe[6];
    fe[0] = (ts - arr) / (dep - arr);
    fe[1] = ts / tot;
    fe[2] = fmodf(fe[1], 2.f); fe[3] = fmodf(fe[1], 4.f); fe[4] = fmodf(fe[1], 7.f);
    fe[5] = hard[m];
    float acc = b1[f];
    #pragma unroll
    for (int k = 0; k < 6; k++) acc += fe[k] * W1[k * HH + f];
    out[(long)m * HH + f] = acc;
}

// ---------------- masked softmax -> unnormalized exp + 1/rowsum -----------------
__device__ __forceinline__ float lrelu(float x) { return x > 0.f ? x : 0.2f * x; }

__device__ __forceinline__ float warp_max(float v) {
    #pragma unroll
    for (int o = 16; o; o >>= 1) v = fmaxf(v, __shfl_xor_sync(0xffffffffu, v, o));
    return v;
}
__device__ __forceinline__ float warp_sum(float v) {
    #pragma unroll
    for (int o = 16; o; o >>= 1) v += __shfl_xor_sync(0xffffffffu, v, o);
    return v;
}

__global__ void alpha_kernel(const float* __restrict__ es,
                             const float* __restrict__ ed,
                             float* __restrict__ inv) {
    __shared__ float    ses[NN];
    __shared__ unsigned smask[NW];
    __shared__ float    red[8];
    int t = blockIdx.x, b = blockIdx.y, tid = threadIdx.x;
    int lane = tid & 31, wrp = tid >> 5;
    const float* esb = es + b * NN;
    const unsigned* mrow = g_maskbits + ((long)b * NN + t) * NW;
    for (int i = tid; i < NN; i += 256) ses[i] = esb[i];
    if (tid < NW) smask[tid] = mrow[tid];
    __syncthreads();

    float edv = ed[b * NN + t];
    float mx = -1e30f;
    for (int s = tid; s < NN; s += 256)
        if ((smask[s >> 5] >> (s & 31)) & 1u) mx = fmaxf(mx, ses[s]);
    mx = warp_max(mx);
    if (lane == 0) red[wrp] = mx;
    __syncthreads();
    float m8 = (lane < 8) ? red[lane] : -1e30f;
    float mlog = lrelu(edv + warp_max(m8));
    __syncthreads();

    float* arow = g_alpha + ((long)b * NN + t) * NN;
    float sum = 0.f;
    for (int s = tid; s < NN; s += 256) {
        float v = 0.f;
        if ((smask[s >> 5] >> (s & 31)) & 1u)
            v = __expf(lrelu(edv + ses[s]) - mlog);
        arow[s] = v;
        sum += v;
    }
    sum = warp_sum(sum);
    if (lane == 0) red[wrp] = sum;
    __syncthreads();
    if (tid == 0) {
        float tot = red[0] + red[1] + red[2] + red[3] + red[4] + red[5] + red[6] + red[7];
        inv[b * NN + t] = 1.f / tot;
    }
}

// ---------------- fused weight transposes [K,N] -> [N,K], grid.z selects --------
__global__ void transpose_all(const float* __restrict__ w0, float* __restrict__ o0,
                              const float* __restrict__ w1, float* __restrict__ o1,
                              const float* __restrict__ w2, float* __restrict__ o2,
                              const float* __restrict__ w3, float* __restrict__ o3,
                              const float* __restrict__ w4, float* __restrict__ o4,
                              const float* __restrict__ w5, float* __restrict__ o5) {
    __shared__ float t[32][33];
    const float* in; float* out; int K, N;
    switch (blockIdx.z) {
        case 0: in = w0; out = o0; K = HH; N = HH; break;
        case 1: in = w1; out = o1; K = HH; N = H2; break;
        case 2: in = w2; out = o2; K = H2; N = H2; break;
        case 3: in = w3; out = o3; K = H2; N = HH; break;
        case 4: in = w4; out = o4; K = HH; N = HH; break;
        default: in = w5; out = o5; K = HH; N = HH; break;
    }
    int n0 = blockIdx.x * 32, k0 = blockIdx.y * 32;
    if (n0 >= N || k0 >= K) return;
    int x = threadIdx.x;
    for (int y = threadIdx.y; y < 32; y += 8)
        t[y][x] = in[(long)(k0 + y) * N + n0 + x];
    __syncthreads();
    for (int y = threadIdx.y; y < 32; y += 8)
        out[(long)(n0 + y) * K + k0 + x] = t[x][y];
}

// ---------------- host orchestration --------------------------------------------
static void gemmTC(const float* A, const float* BT, const float* bias, const float* res,
                   const float* presc, const float* postsc,
                   const float* asrc, const float* adst, float* es, float* ed,
                   float* C, int M, int K, int N, int ldbt, int relu,
                   int transC, int ldct, long sA, long sB, long sC, int rowOff, int batch) {
    dim3 grid(N / GN, M / GM, batch);
    tc_gemm<<<grid, GT, SMEM_BYTES>>>(A, BT, bias, res, presc, postsc, asrc, adst,
                                      es, ed, C, M, K, N, ldbt, relu, transC, ldct,
                                      sA, sB, sC, rowOff);
}

extern "C" void kernel_launch(void* const* d_in, const int* in_sizes, int n_in,
                              void* d_out, int out_size) {
    const int*   adj      = (const int*)d_in[0];
    const float* arrivals = (const float*)d_in[1];
    const float* departs  = (const float*)d_in[2];
    const float* hard     = (const float*)d_in[3];
    const float* active   = (const float*)d_in[4];
    const float* timestep = (const float*)d_in[5];
    const float* total    = (const float*)d_in[6];
    const float* emb_W1 = (const float*)d_in[7],  *emb_b1 = (const float*)d_in[8];
    const float* emb_W2 = (const float*)d_in[9],  *emb_b2 = (const float*)d_in[10];
    const float* gW0 = (const float*)d_in[11], *ga0s = (const float*)d_in[12],
               * ga0d = (const float*)d_in[13], *gb0 = (const float*)d_in[14];
    const float* gW1 = (const float*)d_in[15], *ga1s = (const float*)d_in[16],
               * ga1d = (const float*)d_in[17], *gb1 = (const float*)d_in[18];
    const float* gW2 = (const float*)d_in[19], *ga2s = (const float*)d_in[20],
               * ga2d = (const float*)d_in[21], *gb2 = (const float*)d_in[22];
    const float* fW1 = (const float*)d_in[23], *fb1 = (const float*)d_in[24];
    const float* fW2 = (const float*)d_in[25], *fb2 = (const float*)d_in[26];
    float* out = (float*)d_out;

    cudaFuncSetAttribute(tc_gemm, cudaFuncAttributeMaxDynamicSharedMemorySize, SMEM_BYTES);

    float *px, *pt, *ph, *phwT, *palpha, *pesd, *pinv;
    float *pW2T, *pW0T, *pW1T, *pgW2T, *pf1T, *pf2T;
    cudaGetSymbolAddress((void**)&px, g_x);
    cudaGetSymbolAddress((void**)&pt, g_t);
    cudaGetSymbolAddress((void**)&ph, g_h);
    cudaGetSymbolAddress((void**)&phwT, g_hwT);
    cudaGetSymbolAddress((void**)&palpha, g_alpha);
    cudaGetSymbolAddress((void**)&pesd, g_esd);
    cudaGetSymbolAddress((void**)&pinv, g_inv);
    cudaGetSymbolAddress((void**)&pW2T, g_embW2T);
    cudaGetSymbolAddress((void**)&pW0T, g_W0T);
    cudaGetSymbolAddress((void**)&pW1T, g_W1T);
    cudaGetSymbolAddress((void**)&pgW2T, g_W2T);
    cudaGetSymbolAddress((void**)&pf1T, g_fW1T);
    cudaGetSymbolAddress((void**)&pf2T, g_fW2T);
    float* pes = pesd;
    float* ped = pesd + MM;

    // 1. all weight transposes in one launch
    {
        dim3 grid(32, 32, 6), blk(32, 8);
        transpose_all<<<grid, blk>>>(emb_W2, pW2T, gW0, pW0T, gW1, pW1T,
                                     gW2, pgW2T, fW1, pf1T, fW2, pf2T);
    }
    // 2. mask
    { dim3 grid(NN/32, NN/32, BB), blk(32, 32); mask_kernel<<<grid, blk>>>(adj); }
    // 3. embedding
    embed1_kernel<<<MM, HH>>>(arrivals, departs, hard, timestep, total, emb_W1, emb_b1, pt);
    gemmTC(pt, pW2T, emb_b2, nullptr, nullptr, nullptr, nullptr, nullptr, nullptr, nullptr,
           px, MM, HH, HH, HH, 0, 0, 0, 0, 0, 0, 0, 1);

    const long sAl = (long)NN * NN;
    struct Layer {
        const float *Ain, *WT, *as, *ad, *bias; int Kf, Nf; float* aggC; const float* resid; int relu;
    } L[3] = {
        { px, pW0T,  ga0s, ga0d, gb0, HH, H2, ph, nullptr, 1 },
        { ph, pW1T,  ga1s, ga1d, gb1, H2, H2, ph, nullptr, 1 },
        { ph, pgW2T, ga2s, ga2d, gb2, H2, HH, pt, px,      0 },
    };
    for (int l = 0; l < 3; l++) {
        cudaMemsetAsync(pesd, 0, 2 * MM * sizeof(float));
        // hw = A @ W, written transposed to g_hwT; es/ed accumulated in epilogue
        gemmTC(L[l].Ain, L[l].WT, nullptr, nullptr, nullptr, nullptr,
               L[l].as, L[l].ad, pes, ped,
               phwT, MM, L[l].Kf, L[l].Nf, L[l].Kf, 0, 1, MM, 0, 0, 0, 0, 1);
        // masked softmax -> unnormalized alpha + inv rowsum
        { dim3 grid(NN, BB); alpha_kernel<<<grid, 256>>>(pes, ped, pinv); }
        // aggregation: (U @ hw) * inv + bias [+relu] [+residual]
        gemmTC(palpha, phwT, L[l].bias, L[l].resid, pinv, nullptr,
               nullptr, nullptr, nullptr, nullptr,
               L[l].aggC, NN, NN, L[l].Nf, MM, L[l].relu, 0, 0,
               sAl, (long)NN, (long)NN * L[l].Nf, NN, BB);
    }

    // FF residuals: x += relu(x@W+b) twice; final * active
    gemmTC(pt, pf1T, fb1, pt, nullptr, nullptr, nullptr, nullptr, nullptr, nullptr,
           ph, MM, HH, HH, HH, 1, 0, 0, 0, 0, 0, 0, 1);
    gemmTC(ph, pf2T, fb2, ph, nullptr, active, nullptr, nullptr, nullptr, nullptr,
           out, MM, HH, HH, HH, 1, 0, 0, 0, 0, 0, 0, 1);
}

// round 9
// speedup vs baseline: 2.7648x; 1.2487x over previous
#include <cuda_runtime.h>
#include <cuda_bf16.h>
#include <cstdint>
#include <math.h>

// ---------------- problem constants ----------------
#define BB 8
#define NN 2048
#define HH 512
#define H2 1024
#define MM (BB * NN)          // 16384 rows total
#define NW (NN / 32)

// ---------------- GEMM tile config ----------------
#define GM 128
#define GN 128
#define GK 32
#define GT 256
#define SLAB 4096                      // floats per staged operand slab
#define SMEM_BYTES (4 * SLAB * 4)      // A0 A1 B0 B1 = 64 KB

// ---------------- static device scratch ----------------
__device__ float    g_x[(long)MM * HH];
__device__ float    g_t[(long)MM * HH];
__device__ float    g_h[(long)MM * H2];
__device__ float    g_hwT[(long)H2 * MM];            // transposed hw: [F][16384]
__device__ float    g_alpha[(long)BB * NN * NN];     // unnormalized exp
__device__ float    g_esd[2 * MM];                   // es | ed fused
__device__ float    g_inv[MM];
__device__ unsigned g_maskbits[(long)BB * NN * NW];
__device__ float    g_embW2T[HH * HH];
__device__ float    g_W0T[H2 * HH];
__device__ float    g_W1T[H2 * H2];
__device__ float    g_W2T[HH * H2];
__device__ float    g_fW1T[HH * HH];
__device__ float    g_fW2T[HH * HH];

__device__ __forceinline__ float tf32r(float x) {
    float y; asm("cvt.rna.tf32.f32 %0, %1;" : "=f"(y) : "f"(x)); return y;
}

// mma.sync m16n8k8 tf32 (baseline PTX, lowered to HMMA on sm_103)
__device__ __forceinline__ void mma8(float* c, const uint32_t* a, const uint32_t* b) {
    asm volatile(
        "mma.sync.aligned.m16n8k8.row.col.f32.tf32.tf32.f32 "
        "{%0,%1,%2,%3}, {%4,%5,%6,%7}, {%8,%9}, {%0,%1,%2,%3};"
        : "+f"(c[0]), "+f"(c[1]), "+f"(c[2]), "+f"(c[3])
        : "r"(a[0]), "r"(a[1]), "r"(a[2]), "r"(a[3]), "r"(b[0]), "r"(b[1]));
}

// ---------------- staging: global -> reg-major fragment SMEM (swizzled) ---------
// A tile (kk,mt) = 128 floats = 32 chunks of 16B. chunk C = (kk*8+mt)*32 + reg*8 + gid,
// reg = half + 2*chalf, gid = row&7. Swizzle: C' = C ^ ((kk<<1)|chalf).
// Staging thread holds (row, 4 consecutive cols) = one 16B chunk -> STS.128,
// conflict-free after swizzle. Compute loads LDS.32 at float (C'<<2)+r.
__device__ __forceinline__ void ldgA(const float* __restrict__ Ag, long ld,
                                     float4 v[4], int tid) {
    #pragma unroll
    for (int i = 0; i < 4; i++) {
        int e = tid + i * 256;
        int row = e >> 3, c4 = (e & 7) << 2;
        v[i] = *(const float4*)(Ag + (long)row * ld + c4);
    }
}
__device__ __forceinline__ void stsA(float* __restrict__ sA, const float4 v[4], int tid) {
    #pragma unroll
    for (int i = 0; i < 4; i++) {
        int e = tid + i * 256;
        int row = e >> 3, c4 = (e & 7) << 2;
        int kk = c4 >> 3, chalf = (c4 >> 2) & 1;
        int mt = row >> 4, gid = row & 7, half = (row >> 3) & 1;
        int reg = half + (chalf << 1);
        int C = ((kk << 3) + mt) * 32 + (reg << 3) + gid;
        int s = (kk << 1) | chalf;
        float4 w = make_float4(tf32r(v[i].x), tf32r(v[i].y), tf32r(v[i].z), tf32r(v[i].w));
        *(float4*)(sA + ((C ^ s) << 2)) = w;
    }
}
// B tile (kk,nt) = 64 floats = 16 chunks. chunk C = (kk*16+nt)*16 + reg*8 + gid,
// reg = (k>>2)&1, gid = n&7. Swizzle: C' = C ^ ((kk<<1)|reg).
__device__ __forceinline__ void ldgB(const float* __restrict__ Bg, long ld,
                                     float4 v[4], int tid) {
    #pragma unroll
    for (int i = 0; i < 4; i++) {
        int e = tid + i * 256;
        int n = e >> 3, k4 = (e & 7) << 2;
        v[i] = *(const float4*)(Bg + (long)n * ld + k4);
    }
}
__device__ __forceinline__ void stsB(float* __restrict__ sB, const float4 v[4], int tid) {
    #pragma unroll
    for (int i = 0; i < 4; i++) {
        int e = tid + i * 256;
        int n = e >> 3, k4 = (e & 7) << 2;
        int kk = k4 >> 3, reg = (k4 >> 2) & 1;
        int nt = n >> 3, gid = n & 7;
        int C = ((kk << 4) + nt) * 16 + (reg << 3) + gid;
        int s = (kk << 1) | reg;
        float4 w = make_float4(tf32r(v[i].x), tf32r(v[i].y), tf32r(v[i].z), tf32r(v[i].w));
        *(float4*)(sB + ((C ^ s) << 2)) = w;
    }
}

// ---------------- mma.sync tf32 GEMM --------------------------------------------
__global__ void __launch_bounds__(GT)
tc_gemm(const float* __restrict__ A, const float* __restrict__ BT,
        const float* __restrict__ bias, const float* __restrict__ res,
        const float* __restrict__ prescale, const float* __restrict__ postscale,
        const float* __restrict__ asrc, const float* __restrict__ adst,
        float* __restrict__ es, float* __restrict__ ed,
        float* __restrict__ C, int M, int K, int N, int ldbt,
        int relu, int transC, int ldct,
        long sA_, long sB_, long sC_, int rowOff) {
    extern __shared__ float smem[];
    int tid = threadIdx.x, lane = tid & 31, w = tid >> 5;
    int wm = w & 3, wn = w >> 2;              // 4 warps along M, 2 along N
    int gid = lane >> 2, tig = lane & 3;
    int q = lane >> 2, r = lane & 3;          // chunk-sub indices for LDS.32
    int bz = blockIdx.z;
    A += bz * sA_; BT += bz * sB_; C += bz * sC_;
    if (res) res += bz * sC_;
    int ro = bz * rowOff;
    if (prescale) prescale += ro;
    if (postscale) postscale += ro;
    if (es) { es += ro; ed += ro; }

    int m0 = blockIdx.y * GM, n0 = blockIdx.x * GN;
    const float* Ab = A + (long)m0 * K;
    const float* Bb = BT + (long)n0 * ldbt;
    int nc = K / GK;

    float acc[2][8][4];
    #pragma unroll
    for (int i = 0; i < 2; i++)
        #pragma unroll
        for (int j = 0; j < 8; j++)
            #pragma unroll
            for (int p = 0; p < 4; p++) acc[i][j][p] = 0.f;

    {
        float4 va[4], vb[4];
        ldgA(Ab, K, va, tid); ldgB(Bb, ldbt, vb, tid);
        stsA(smem, va, tid);  stsB(smem + 2 * SLAB, vb, tid);
    }
    __syncthreads();

    for (int c = 0; c < nc; c++) {
        float4 va[4], vb[4];
        if (c + 1 < nc) {
            ldgA(Ab + (c + 1) * GK, K, va, tid);
            ldgB(Bb + (c + 1) * GK, ldbt, vb, tid);
        }
        const float* cA = smem + (c & 1) * SLAB;
        const float* cB = smem + 2 * SLAB + (c & 1) * SLAB;
        #pragma unroll
        for (int kk = 0; kk < 4; kk++) {
            uint32_t af[2][4];
            #pragma unroll
            for (int mt = 0; mt < 2; mt++) {
                #pragma unroll
                for (int reg = 0; reg < 4; reg++) {
                    int s = (kk << 1) | (reg >> 1);
                    int cb = ((kk << 3) + wm * 2 + mt) * 32 + (reg << 3);
                    af[mt][reg] = __float_as_uint(cA[((cb + (q ^ s)) << 2) + r]);
                }
            }
            #pragma unroll
            for (int nt = 0; nt < 8; nt++) {
                uint32_t bf[2];
                #pragma unroll
                for (int reg = 0; reg < 2; reg++) {
                    int s = (kk << 1) | reg;
                    int cb = ((kk << 4) + wn * 8 + nt) * 16 + (reg << 3);
                    bf[reg] = __float_as_uint(cB[((cb + (q ^ s)) << 2) + r]);
                }
                mma8(acc[0][nt], af[0], bf);
                mma8(acc[1][nt], af[1], bf);
            }
        }
        if (c + 1 < nc) {
            int nb = (c + 1) & 1;
            stsA(smem + nb * SLAB, va, tid);
            stsB(smem + 2 * SLAB + nb * SLAB, vb, tid);
        }
        __syncthreads();
    }

    // epilogue
    #pragma unroll
    for (int mt = 0; mt < 2; mt++) {
        #pragma unroll
        for (int half = 0; half < 2; half++) {
            int rr = m0 + wm * 32 + mt * 16 + half * 8 + gid;
            float presv = prescale ? prescale[rr] : 1.f;
            float postv = postscale ? postscale[rr] : 1.f;
            float se = 0.f, sd = 0.f;
            #pragma unroll
            for (int nt = 0; nt < 8; nt++) {
                int cidx = n0 + wn * 64 + nt * 8 + tig * 2;
                float v0 = acc[mt][nt][half * 2 + 0] * presv;
                float v1 = acc[mt][nt][half * 2 + 1] * presv;
                if (bias) { v0 += bias[cidx]; v1 += bias[cidx + 1]; }
                if (relu) { v0 = fmaxf(v0, 0.f); v1 = fmaxf(v1, 0.f); }
                if (res) {
                    float2 rv = *(const float2*)(res + (long)rr * N + cidx);
                    v0 += rv.x; v1 += rv.y;
                }
                v0 *= postv; v1 *= postv;
                if (asrc) {
                    se += v0 * asrc[cidx] + v1 * asrc[cidx + 1];
                    sd += v0 * adst[cidx] + v1 * adst[cidx + 1];
                }
                if (transC) {
                    C[(long)cidx * ldct + rr] = v0;
                    C[(long)(cidx + 1) * ldct + rr] = v1;
                } else {
                    *(float2*)(C + (long)rr * N + cidx) = make_float2(v0, v1);
                }
            }
            if (es) { atomicAdd(es + rr, se); atomicAdd(ed + rr, sd); }
        }
    }
}

// ---------------- mask transpose + bitpack --------------------------------------
__global__ void mask_kernel(const int* __restrict__ adj) {
    __shared__ int tile[32][33];
    int b = blockIdx.z;
    int t0 = blockIdx.x * 32, s0 = blockIdx.y * 32;
    tile[threadIdx.y][threadIdx.x] =
        adj[((long)b * NN + (s0 + threadIdx.y)) * NN + t0 + threadIdx.x];
    __syncthreads();
    if (threadIdx.y == 0) {
        int t = t0 + threadIdx.x;
        unsigned w = 0u;
        #pragma unroll
        for (int i = 0; i < 32; i++) {
            int s = s0 + i;
            if (tile[i][threadIdx.x] != 0 || s == t) w |= (1u << i);
        }
        g_maskbits[((long)b * NN + t) * NW + (s0 >> 5)] = w;
    }
}

// ---------------- features + first embedding linear (K=6) -----------------------
__global__ void embed1_kernel(const float* __restrict__ arrivals,
                              const float* __restrict__ departures,
                              const float* __restrict__ hard,
                              const float* __restrict__ timestep,
                              const float* __restrict__ total,
                              const float* __restrict__ W1,
                              const float* __restrict__ b1,
                              float* __restrict__ out) {
    int m = blockIdx.x, f = threadIdx.x;
    int b = m / NN;
    float ts = timestep[b], tot = total[b];
    float arr = arrivals[m], dep = departures[m];
    float fe[6];
    fe[0] = (ts - arr) / (dep - arr);
    fe[1] = ts / tot;
    fe[2] = fmodf(fe[1], 2.f); fe[3] = fmodf(fe[1], 4.f); fe[4] = fmodf(fe[1], 7.f);
    fe[5] = hard[m];
    float acc = b1[f];
    #pragma unroll
    for (int k = 0; k < 6; k++) acc += fe[k] * W1[k * HH + f];
    out[(long)m * HH + f] = acc;
}

// ---------------- masked softmax -> unnormalized exp + 1/rowsum -----------------
__device__ __forceinline__ float lrelu(float x) { return x > 0.f ? x : 0.2f * x; }

__device__ __forceinline__ float warp_max(float v) {
    #pragma unroll
    for (int o = 16; o; o >>= 1) v = fmaxf(v, __shfl_xor_sync(0xffffffffu, v, o));
    return v;
}
__device__ __forceinline__ float warp_sum(float v) {
    #pragma unroll
    for (int o = 16; o; o >>= 1) v += __shfl_xor_sync(0xffffffffu, v, o);
    return v;
}

__global__ void alpha_kernel(const float* __restrict__ es,
                             const float* __restrict__ ed,
                             float* __restrict__ inv) {
    __shared__ float    ses[NN];
    __shared__ unsigned smask[NW];
    __shared__ float    red[8];
    int t = blockIdx.x, b = blockIdx.y, tid = threadIdx.x;
    int lane = tid & 31, wrp = tid >> 5;
    const float* esb = es + b * NN;
    const unsigned* mrow = g_maskbits + ((long)b * NN + t) * NW;
    for (int i = tid; i < NN; i += 256) ses[i] = esb[i];
    if (tid < NW) smask[tid] = mrow[tid];
    __syncthreads();

    float edv = ed[b * NN + t];
    float mx = -1e30f;
    for (int s = tid; s < NN; s += 256)
        if ((smask[s >> 5] >> (s & 31)) & 1u) mx = fmaxf(mx, ses[s]);
    mx = warp_max(mx);
    if (lane == 0) red[wrp] = mx;
    __syncthreads();
    float m8 = (lane < 8) ? red[lane] : -1e30f;
    float mlog = lrelu(edv + warp_max(m8));
    __syncthreads();

    float* arow = g_alpha + ((long)b * NN + t) * NN;
    float sum = 0.f;
    for (int s = tid; s < NN; s += 256) {
        float v = 0.f;
        if ((smask[s >> 5] >> (s & 31)) & 1u)
            v = __expf(lrelu(edv + ses[s]) - mlog);
        arow[s] = v;
        sum += v;
    }
    sum = warp_sum(sum);
    if (lane == 0) red[wrp] = sum;
    __syncthreads();
    if (tid == 0) {
        float tot = red[0] + red[1] + red[2] + red[3] + red[4] + red[5] + red[6] + red[7];
        inv[b * NN + t] = 1.f / tot;
    }
}

// ---------------- fused weight transposes [K,N] -> [N,K], grid.z selects --------
__global__ void transpose_all(const float* __restrict__ w0, float* __restrict__ o0,
                              const float* __restrict__ w1, float* __restrict__ o1,
                              const float* __restrict__ w2, float* __restrict__ o2,
                              const float* __restrict__ w3, float* __restrict__ o3,
                              const float* __restrict__ w4, float* __restrict__ o4,
                              const float* __restrict__ w5, float* __restrict__ o5) {
    __shared__ float t[32][33];
    const float* in; float* out; int K, N;
    switch (blockIdx.z) {
        case 0: in = w0; out = o0; K = HH; N = HH; break;
        case 1: in = w1; out = o1; K = HH; N = H2; break;
        case 2: in = w2; out = o2; K = H2; N = H2; break;
        case 3: in = w3; out = o3; K = H2; N = HH; break;
        case 4: in = w4; out = o4; K = HH; N = HH; break;
        default: in = w5; out = o5; K = HH; N = HH; break;
    }
    int n0 = blockIdx.x * 32, k0 = blockIdx.y * 32;
    if (n0 >= N || k0 >= K) return;
    int x = threadIdx.x;
    for (int y = threadIdx.y; y < 32; y += 8)
        t[y][x] = in[(long)(k0 + y) * N + n0 + x];
    __syncthreads();
    for (int y = threadIdx.y; y < 32; y += 8)
        out[(long)(n0 + y) * K + k0 + x] = t[x][y];
}

// ---------------- host orchestration --------------------------------------------
static void gemmTC(const float* A, const float* BT, const float* bias, const float* res,
                   const float* presc, const float* postsc,
                   const float* asrc, const float* adst, float* es, float* ed,
                   float* C, int M, int K, int N, int ldbt, int relu,
                   int transC, int ldct, long sA, long sB, long sC, int rowOff, int batch) {
    dim3 grid(N / GN, M / GM, batch);
    tc_gemm<<<grid, GT, SMEM_BYTES>>>(A, BT, bias, res, presc, postsc, asrc, adst,
                                      es, ed, C, M, K, N, ldbt, relu, transC, ldct,
                                      sA, sB, sC, rowOff);
}

extern "C" void kernel_launch(void* const* d_in, const int* in_sizes, int n_in,
                              void* d_out, int out_size) {
    const int*   adj      = (const int*)d_in[0];
    const float* arrivals = (const float*)d_in[1];
    const float* departs  = (const float*)d_in[2];
    const float* hard     = (const float*)d_in[3];
    const float* active   = (const float*)d_in[4];
    const float* timestep = (const float*)d_in[5];
    const float* total    = (const float*)d_in[6];
    const float* emb_W1 = (const float*)d_in[7],  *emb_b1 = (const float*)d_in[8];
    const float* emb_W2 = (const float*)d_in[9],  *emb_b2 = (const float*)d_in[10];
    const float* gW0 = (const float*)d_in[11], *ga0s = (const float*)d_in[12],
               * ga0d = (const float*)d_in[13], *gb0 = (const float*)d_in[14];
    const float* gW1 = (const float*)d_in[15], *ga1s = (const float*)d_in[16],
               * ga1d = (const float*)d_in[17], *gb1 = (const float*)d_in[18];
    const float* gW2 = (const float*)d_in[19], *ga2s = (const float*)d_in[20],
               * ga2d = (const float*)d_in[21], *gb2 = (const float*)d_in[22];
    const float* fW1 = (const float*)d_in[23], *fb1 = (const float*)d_in[24];
    const float* fW2 = (const float*)d_in[25], *fb2 = (const float*)d_in[26];
    float* out = (float*)d_out;

    cudaFuncSetAttribute(tc_gemm, cudaFuncAttributeMaxDynamicSharedMemorySize, SMEM_BYTES);

    float *px, *pt, *ph, *phwT, *palpha, *pesd, *pinv;
    float *pW2T, *pW0T, *pW1T, *pgW2T, *pf1T, *pf2T;
    cudaGetSymbolAddress((void**)&px, g_x);
    cudaGetSymbolAddress((void**)&pt, g_t);
    cudaGetSymbolAddress((void**)&ph, g_h);
    cudaGetSymbolAddress((void**)&phwT, g_hwT);
    cudaGetSymbolAddress((void**)&palpha, g_alpha);
    cudaGetSymbolAddress((void**)&pesd, g_esd);
    cudaGetSymbolAddress((void**)&pinv, g_inv);
    cudaGetSymbolAddress((void**)&pW2T, g_embW2T);
    cudaGetSymbolAddress((void**)&pW0T, g_W0T);
    cudaGetSymbolAddress((void**)&pW1T, g_W1T);
    cudaGetSymbolAddress((void**)&pgW2T, g_W2T);
    cudaGetSymbolAddress((void**)&pf1T, g_fW1T);
    cudaGetSymbolAddress((void**)&pf2T, g_fW2T);
    float* pes = pesd;
    float* ped = pesd + MM;

    // 1. all weight transposes in one launch
    {
        dim3 grid(32, 32, 6), blk(32, 8);
        transpose_all<<<grid, blk>>>(emb_W2, pW2T, gW0, pW0T, gW1, pW1T,
                                     gW2, pgW2T, fW1, pf1T, fW2, pf2T);
    }
    // 2. mask
    { dim3 grid(NN/32, NN/32, BB), blk(32, 32); mask_kernel<<<grid, blk>>>(adj); }
    // 3. embedding
    embed1_kernel<<<MM, HH>>>(arrivals, departs, hard, timestep, total, emb_W1, emb_b1, pt);
    gemmTC(pt, pW2T, emb_b2, nullptr, nullptr, nullptr, nullptr, nullptr, nullptr, nullptr,
           px, MM, HH, HH, HH, 0, 0, 0, 0, 0, 0, 0, 1);

    const long sAl = (long)NN * NN;
    struct Layer {
        const float *Ain, *WT, *as, *ad, *bias; int Kf, Nf; float* aggC; const float* resid; int relu;
    } L[3] = {
        { px, pW0T,  ga0s, ga0d, gb0, HH, H2, ph, nullptr, 1 },
        { ph, pW1T,  ga1s, ga1d, gb1, H2, H2, ph, nullptr, 1 },
        { ph, pgW2T, ga2s, ga2d, gb2, H2, HH, pt, px,      0 },
    };
    for (int l = 0; l < 3; l++) {
        cudaMemsetAsync(pesd, 0, 2 * MM * sizeof(float));
        // hw = A @ W, written transposed to g_hwT; es/ed accumulated in epilogue
        gemmTC(L[l].Ain, L[l].WT, nullptr, nullptr, nullptr, nullptr,
               L[l].as, L[l].ad, pes, ped,
               phwT, MM, L[l].Kf, L[l].Nf, L[l].Kf, 0, 1, MM, 0, 0, 0, 0, 1);
        // masked softmax -> unnormalized alpha + inv rowsum
        { dim3 grid(NN, BB); alpha_kernel<<<grid, 256>>>(pes, ped, pinv); }
        // aggregation: (U @ hw) * inv + bias [+relu] [+residual]
        gemmTC(palpha, phwT, L[l].bias, L[l].resid, pinv, nullptr,
               nullptr, nullptr, nullptr, nullptr,
               L[l].aggC, NN, NN, L[l].Nf, MM, L[l].relu, 0, 0,
               sAl, (long)NN, (long)NN * L[l].Nf, NN, BB);
    }

    // FF residuals: x += relu(x@W+b) twice; final * active
    gemmTC(pt, pf1T, fb1, pt, nullptr, nullptr, nullptr, nullptr, nullptr, nullptr,
           ph, MM, HH, HH, HH, 1, 0, 0, 0, 0, 0, 0, 1);
    gemmTC(ph, pf2T, fb2, ph, nullptr, active, nullptr, nullptr, nullptr, nullptr,
           out, MM, HH, HH, HH, 1, 0, 0, 0, 0, 0, 0, 1);
}